// round 1
// baseline (speedup 1.0000x reference)
#include <cuda_runtime.h>
#include <math.h>

#define NB 8
#define C 256
#define HW 1024
#define TN 1024
#define HIDDEN 1024

// ---------------- scratch (device globals; no allocation allowed) ----------------
__device__ float g_qbranch[NB*C*HW];
__device__ float g_kvbranch[NB*C*HW];
__device__ float g_tmp[NB*C*HW];
__device__ float g_qb[NB*C*HW];
__device__ float g_kb[NB*C*HW];
__device__ float g_vb[NB*C*HW];
__device__ float g_attn[NB*C*HW];
__device__ float g_h1[NB*HIDDEN*HW];
__device__ float g_h2[NB*HIDDEN*HW];

// ---------------- batched SGEMM: C[b] = A[MxK] @ B[b][KxTN] (+ add) ----------------
// grid: (TN/64, M/64, NB), block 256. A shared across batch.
__global__ __launch_bounds__(256) void sgemm64(
    const float* __restrict__ A, const float* __restrict__ B,
    float* Cd, const float* addp, int M, int K)
{
    __shared__ float As[16][64];
    __shared__ float Bs[16][64];
    int bn = blockIdx.x * 64;
    int bm = blockIdx.y * 64;
    int b  = blockIdx.z;
    const float* Bb = B + (size_t)b * K * TN;
    float*       Cb = Cd + (size_t)b * M * TN;
    const float* addb = addp ? addp + (size_t)b * M * TN : nullptr;

    int tid = threadIdx.x;
    int tx = tid & 15, ty = tid >> 4;
    int am = tid >> 2, ak = (tid & 3) << 2;
    int bln = tid & 63, blk = tid >> 6;

    float acc[4][4] = {};
    for (int kk = 0; kk < K; kk += 16) {
        float4 a4 = *(const float4*)(A + (size_t)(bm + am) * K + kk + ak);
        As[ak+0][am] = a4.x; As[ak+1][am] = a4.y;
        As[ak+2][am] = a4.z; As[ak+3][am] = a4.w;
        #pragma unroll
        for (int i = 0; i < 4; i++)
            Bs[blk + 4*i][bln] = Bb[(size_t)(kk + blk + 4*i) * TN + bn + bln];
        __syncthreads();
        #pragma unroll
        for (int k = 0; k < 16; k++) {
            float4 av = *(const float4*)&As[k][ty << 2];
            float4 bv = *(const float4*)&Bs[k][tx << 2];
            acc[0][0] += av.x*bv.x; acc[0][1] += av.x*bv.y; acc[0][2] += av.x*bv.z; acc[0][3] += av.x*bv.w;
            acc[1][0] += av.y*bv.x; acc[1][1] += av.y*bv.y; acc[1][2] += av.y*bv.z; acc[1][3] += av.y*bv.w;
            acc[2][0] += av.z*bv.x; acc[2][1] += av.z*bv.y; acc[2][2] += av.z*bv.z; acc[2][3] += av.z*bv.w;
            acc[3][0] += av.w*bv.x; acc[3][1] += av.w*bv.y; acc[3][2] += av.w*bv.z; acc[3][3] += av.w*bv.w;
        }
        __syncthreads();
    }
    #pragma unroll
    for (int i = 0; i < 4; i++) {
        size_t row = (size_t)(bm + (ty << 2) + i) * TN + bn + (tx << 2);
        float4 r = make_float4(acc[i][0], acc[i][1], acc[i][2], acc[i][3]);
        if (addb) {
            float4 ad = *(const float4*)(addb + row);
            r.x += ad.x; r.y += ad.y; r.z += ad.z; r.w += ad.w;
        }
        *(float4*)(Cb + row) = r;
    }
}

// ---------------- conv KxK as implicit GEMM (im2col gather in B-load) ----------------
// Y[b][oc][y][x] = sum_ic,tap W[oc][ic*KK+tap] * X[b][ic][y+dy-P][x+dx-P]
template<int KW, int PAD>
__global__ __launch_bounds__(256) void conv_gemm(
    const float* __restrict__ Wt, const float* __restrict__ X, float* __restrict__ Cd)
{
    constexpr int KK2 = KW * KW;
    constexpr int K = C * KK2;
    __shared__ float As[16][64];
    __shared__ float Bs[16][64];
    int bn = blockIdx.x * 64;
    int bm = blockIdx.y * 64;
    int b  = blockIdx.z;
    const float* Xb = X + (size_t)b * C * HW;
    float*       Cb = Cd + (size_t)b * C * HW;

    int tid = threadIdx.x;
    int tx = tid & 15, ty = tid >> 4;
    int am = tid >> 2, ak = (tid & 3) << 2;
    int bln = tid & 63, blk = tid >> 6;
    int n = bn + bln;
    int yy = n >> 5, xx = n & 31;

    float acc[4][4] = {};
    for (int kk = 0; kk < K; kk += 16) {
        float4 a4 = *(const float4*)(Wt + (size_t)(bm + am) * K + kk + ak);
        As[ak+0][am] = a4.x; As[ak+1][am] = a4.y;
        As[ak+2][am] = a4.z; As[ak+3][am] = a4.w;
        #pragma unroll
        for (int i = 0; i < 4; i++) {
            int kg = kk + blk + 4*i;
            int ic = kg / KK2;
            int tap = kg - ic * KK2;
            int dy = tap / KW, dx = tap - dy * KW;
            int iy = yy + dy - PAD, ix = xx + dx - PAD;
            float v = 0.f;
            if ((unsigned)iy < 32u && (unsigned)ix < 32u)
                v = Xb[(size_t)ic * HW + (iy << 5) + ix];
            Bs[blk + 4*i][bln] = v;
        }
        __syncthreads();
        #pragma unroll
        for (int k = 0; k < 16; k++) {
            float4 av = *(const float4*)&As[k][ty << 2];
            float4 bv = *(const float4*)&Bs[k][tx << 2];
            acc[0][0] += av.x*bv.x; acc[0][1] += av.x*bv.y; acc[0][2] += av.x*bv.z; acc[0][3] += av.x*bv.w;
            acc[1][0] += av.y*bv.x; acc[1][1] += av.y*bv.y; acc[1][2] += av.y*bv.z; acc[1][3] += av.y*bv.w;
            acc[2][0] += av.z*bv.x; acc[2][1] += av.z*bv.y; acc[2][2] += av.z*bv.z; acc[2][3] += av.z*bv.w;
            acc[3][0] += av.w*bv.x; acc[3][1] += av.w*bv.y; acc[3][2] += av.w*bv.z; acc[3][3] += av.w*bv.w;
        }
        __syncthreads();
    }
    #pragma unroll
    for (int i = 0; i < 4; i++) {
        size_t row = (size_t)(bm + (ty << 2) + i) * TN + bn + (tx << 2);
        float4 r = make_float4(acc[i][0], acc[i][1], acc[i][2], acc[i][3]);
        *(float4*)(Cb + row) = r;
    }
}

// ---------------- layernorm over channel dim (C=256), NCHW ----------------
// grid: (HW/32, NB), block 256 (32 pixels x 8 channel-groups of 32)
__global__ __launch_bounds__(256) void ln_kernel(
    const float* __restrict__ x, const float* __restrict__ w,
    const float* __restrict__ bias, float* __restrict__ y)
{
    int b = blockIdx.y;
    int n0 = blockIdx.x * 32;
    int nx = threadIdx.x & 31;
    int cg = threadIdx.x >> 5;
    const float* xb = x + (size_t)b * C * HW + n0 + nx;

    float v[32];
    float s = 0.f, ss = 0.f;
    #pragma unroll
    for (int i = 0; i < 32; i++) {
        float t = xb[(size_t)(cg * 32 + i) * HW];
        v[i] = t; s += t; ss += t * t;
    }
    __shared__ float rs[8][32], rss[8][32];
    rs[cg][nx] = s; rss[cg][nx] = ss;
    __syncthreads();
    float tot = 0.f, tot2 = 0.f;
    #pragma unroll
    for (int g = 0; g < 8; g++) { tot += rs[g][nx]; tot2 += rss[g][nx]; }
    float mu = tot * (1.f / 256.f);
    float var = tot2 * (1.f / 256.f) - mu * mu;
    float rstd = rsqrtf(var + 1e-5f);

    float* yb = y + (size_t)b * C * HW + n0 + nx;
    #pragma unroll
    for (int i = 0; i < 32; i++) {
        int c = cg * 32 + i;
        yb[(size_t)c * HW] = (v[i] - mu) * rstd * w[c] + bias[c];
    }
}

// ---------------- fused flash attention (d=64, N=1024, per (b,head)) ----------------
// grid: (16 q-tiles, 4 heads, 8 batch), block 256, dynamic smem 67584B
__global__ __launch_bounds__(256) void attn64(
    const float* __restrict__ Q, const float* __restrict__ Kg,
    const float* __restrict__ V, float* __restrict__ O)
{
    extern __shared__ float sm[];
    float (*Qs)[64] = (float(*)[64])(sm);
    float (*Ks)[64] = (float(*)[64])(sm + 4096);
    float (*Vs)[68] = (float(*)[68])(sm + 8192);
    float (*Ps)[68] = (float(*)[68])(sm + 8192 + 4352);

    int n0 = blockIdx.x * 64;
    size_t base = ((size_t)blockIdx.z * C + (size_t)blockIdx.y * 64) * (size_t)HW;
    const float* Qb = Q + base;
    const float* Kb = Kg + base;
    const float* Vb = V + base;

    int tid = threadIdx.x;
    int tx = tid & 15, ty = tid >> 4;

    for (int idx = tid; idx < 4096; idx += 256) {
        int d = idx >> 6, q = idx & 63;
        Qs[d][q] = Qb[(size_t)d * HW + n0 + q];
    }

    float oacc[4][4] = {};
    float mrun[4], lrun[4];
    #pragma unroll
    for (int i = 0; i < 4; i++) { mrun[i] = -1e30f; lrun[i] = 0.f; }

    for (int m0 = 0; m0 < HW; m0 += 64) {
        __syncthreads();
        for (int idx = tid; idx < 4096; idx += 256) {
            int d = idx >> 6, m = idx & 63;
            Ks[d][m] = Kb[(size_t)d * HW + m0 + m];
            Vs[m][d] = Vb[(size_t)d * HW + m0 + m];
        }
        __syncthreads();

        float s[4][4] = {};
        #pragma unroll 16
        for (int d = 0; d < 64; d++) {
            float4 av = *(const float4*)&Qs[d][ty << 2];
            float4 bv = *(const float4*)&Ks[d][tx << 2];
            s[0][0] += av.x*bv.x; s[0][1] += av.x*bv.y; s[0][2] += av.x*bv.z; s[0][3] += av.x*bv.w;
            s[1][0] += av.y*bv.x; s[1][1] += av.y*bv.y; s[1][2] += av.y*bv.z; s[1][3] += av.y*bv.w;
            s[2][0] += av.z*bv.x; s[2][1] += av.z*bv.y; s[2][2] += av.z*bv.z; s[2][3] += av.z*bv.w;
            s[3][0] += av.w*bv.x; s[3][1] += av.w*bv.y; s[3][2] += av.w*bv.z; s[3][3] += av.w*bv.w;
        }
        #pragma unroll
        for (int i = 0; i < 4; i++)
            #pragma unroll
            for (int j = 0; j < 4; j++) s[i][j] *= 0.125f;  // d^-0.5, d=64

        #pragma unroll
        for (int i = 0; i < 4; i++) {
            float mx = fmaxf(fmaxf(s[i][0], s[i][1]), fmaxf(s[i][2], s[i][3]));
            #pragma unroll
            for (int o = 1; o < 16; o <<= 1)
                mx = fmaxf(mx, __shfl_xor_sync(0xffffffffu, mx, o));
            float mnew = fmaxf(mrun[i], mx);
            float corr = __expf(mrun[i] - mnew);
            float rsum = 0.f;
            #pragma unroll
            for (int j = 0; j < 4; j++) {
                float p = __expf(s[i][j] - mnew);
                s[i][j] = p; rsum += p;
            }
            #pragma unroll
            for (int o = 1; o < 16; o <<= 1)
                rsum += __shfl_xor_sync(0xffffffffu, rsum, o);
            lrun[i] = lrun[i] * corr + rsum;
            mrun[i] = mnew;
            #pragma unroll
            for (int j = 0; j < 4; j++) oacc[i][j] *= corr;
            #pragma unroll
            for (int j = 0; j < 4; j++) Ps[(ty << 2) + i][(tx << 2) + j] = s[i][j];
        }
        __syncthreads();

        #pragma unroll 8
        for (int m = 0; m < 64; m++) {
            float4 bv = *(const float4*)&Vs[m][tx << 2];
            float a0 = Ps[(ty << 2) + 0][m];
            float a1 = Ps[(ty << 2) + 1][m];
            float a2 = Ps[(ty << 2) + 2][m];
            float a3 = Ps[(ty << 2) + 3][m];
            oacc[0][0] += a0*bv.x; oacc[0][1] += a0*bv.y; oacc[0][2] += a0*bv.z; oacc[0][3] += a0*bv.w;
            oacc[1][0] += a1*bv.x; oacc[1][1] += a1*bv.y; oacc[1][2] += a1*bv.z; oacc[1][3] += a1*bv.w;
            oacc[2][0] += a2*bv.x; oacc[2][1] += a2*bv.y; oacc[2][2] += a2*bv.z; oacc[2][3] += a2*bv.w;
            oacc[3][0] += a3*bv.x; oacc[3][1] += a3*bv.y; oacc[3][2] += a3*bv.z; oacc[3][3] += a3*bv.w;
        }
    }

    float* Ob = O + base;
    #pragma unroll
    for (int i = 0; i < 4; i++) {
        float linv = 1.f / lrun[i];
        #pragma unroll
        for (int j = 0; j < 4; j++)
            Ob[(size_t)((tx << 2) + j) * HW + n0 + (ty << 2) + i] = oacc[i][j] * linv;
    }
}

// ---------------- depthwise 3x3 conv + exact GELU ----------------
__global__ __launch_bounds__(256) void dwconv_gelu(
    const float* __restrict__ X, const float* __restrict__ W, float* __restrict__ Y)
{
    int idx = blockIdx.x * 256 + threadIdx.x;   // 8 * 1024 * 1024 total
    int x = idx & 31;
    int y = (idx >> 5) & 31;
    int c = (idx >> 10) & 1023;
    int b = idx >> 20;
    const float* xb = X + ((size_t)b * HIDDEN + c) * HW;
    const float* wc = W + c * 9;
    float acc = 0.f;
    #pragma unroll
    for (int dy = 0; dy < 3; dy++) {
        int iy = y + dy - 1;
        #pragma unroll
        for (int dx = 0; dx < 3; dx++) {
            int ix = x + dx - 1;
            if ((unsigned)iy < 32u && (unsigned)ix < 32u)
                acc += wc[dy * 3 + dx] * xb[(iy << 5) + ix];
        }
    }
    float g = 0.5f * acc * (1.f + erff(acc * 0.70710678118654752440f));
    Y[idx] = g;
}

// ---------------- host orchestration ----------------
extern "C" void kernel_launch(void* const* d_in, const int* in_sizes, int n_in,
                              void* d_out, int out_size)
{
    const float* aop      = (const float*)d_in[0];
    const float* dop      = (const float*)d_in[1];
    const float* w_qconv  = (const float*)d_in[2];
    const float* w_kvconv = (const float*)d_in[3];
    const float* lnq1_w   = (const float*)d_in[4];
    const float* lnq1_b   = (const float*)d_in[5];
    const float* lnkv1_w  = (const float*)d_in[6];
    const float* lnkv1_b  = (const float*)d_in[7];
    const float* lnq2_w   = (const float*)d_in[8];
    const float* lnq2_b   = (const float*)d_in[9];
    const float* lnkv2_w  = (const float*)d_in[10];
    const float* lnkv2_b  = (const float*)d_in[11];
    const float* lnffn_w  = (const float*)d_in[12];
    const float* lnffn_b  = (const float*)d_in[13];
    const float* saq_qkv  = (const float*)d_in[14];
    const float* saq_proj = (const float*)d_in[15];
    const float* sakv_qkv = (const float*)d_in[16];
    const float* sakv_proj= (const float*)d_in[17];
    const float* ca_q     = (const float*)d_in[18];
    const float* ca_k     = (const float*)d_in[19];
    const float* ca_v     = (const float*)d_in[20];
    const float* ca_proj  = (const float*)d_in[21];
    const float* leff_in  = (const float*)d_in[22];
    const float* leff_dw  = (const float*)d_in[23];
    const float* leff_out = (const float*)d_in[24];
    float* out = (float*)d_out;

    float *qbr, *kvbr, *tmp, *qb, *kb, *vb, *att, *h1, *h2;
    cudaGetSymbolAddress((void**)&qbr,  g_qbranch);
    cudaGetSymbolAddress((void**)&kvbr, g_kvbranch);
    cudaGetSymbolAddress((void**)&tmp,  g_tmp);
    cudaGetSymbolAddress((void**)&qb,   g_qb);
    cudaGetSymbolAddress((void**)&kb,   g_kb);
    cudaGetSymbolAddress((void**)&vb,   g_vb);
    cudaGetSymbolAddress((void**)&att,  g_attn);
    cudaGetSymbolAddress((void**)&h1,   g_h1);
    cudaGetSymbolAddress((void**)&h2,   g_h2);

    const int ATTN_SMEM = (4096 + 4096 + 4352 + 4352) * 4;   // 67584 bytes
    cudaFuncSetAttribute(attn64, cudaFuncAttributeMaxDynamicSharedMemorySize, ATTN_SMEM);

    dim3 gC(16, 4, NB);     // M = 256
    dim3 gH(16, 16, NB);    // M = 1024
    dim3 gLN(32, NB);

    // ---- q branch ----
    conv_gemm<3, 1><<<gC, 256>>>(w_qconv, aop, qbr);
    ln_kernel<<<gLN, 256>>>(qbr, lnq1_w, lnq1_b, tmp);
    sgemm64<<<gC, 256>>>(saq_qkv,             tmp, qb, nullptr, C, C);
    sgemm64<<<gC, 256>>>(saq_qkv + C * C,     tmp, kb, nullptr, C, C);
    sgemm64<<<gC, 256>>>(saq_qkv + 2 * C * C, tmp, vb, nullptr, C, C);
    attn64<<<dim3(16, 4, NB), 256, ATTN_SMEM>>>(qb, kb, vb, att);
    sgemm64<<<gC, 256>>>(saq_proj, att, qbr, qbr, C, C);

    // ---- kv branch ----
    conv_gemm<5, 2><<<gC, 256>>>(w_kvconv, dop, kvbr);
    ln_kernel<<<gLN, 256>>>(kvbr, lnkv1_w, lnkv1_b, tmp);
    sgemm64<<<gC, 256>>>(sakv_qkv,             tmp, qb, nullptr, C, C);
    sgemm64<<<gC, 256>>>(sakv_qkv + C * C,     tmp, kb, nullptr, C, C);
    sgemm64<<<gC, 256>>>(sakv_qkv + 2 * C * C, tmp, vb, nullptr, C, C);
    attn64<<<dim3(16, 4, NB), 256, ATTN_SMEM>>>(qb, kb, vb, att);
    sgemm64<<<gC, 256>>>(sakv_proj, att, kvbr, kvbr, C, C);

    // ---- cross attention ----
    ln_kernel<<<gLN, 256>>>(qbr, lnq2_w, lnq2_b, tmp);
    sgemm64<<<gC, 256>>>(ca_q, tmp, qb, nullptr, C, C);
    ln_kernel<<<gLN, 256>>>(kvbr, lnkv2_w, lnkv2_b, tmp);
    sgemm64<<<gC, 256>>>(ca_k, tmp, kb, nullptr, C, C);
    sgemm64<<<gC, 256>>>(ca_v, tmp, vb, nullptr, C, C);
    attn64<<<dim3(16, 4, NB), 256, ATTN_SMEM>>>(qb, kb, vb, att);
    sgemm64<<<gC, 256>>>(ca_proj, att, out, qbr, C, C);   // x = q_branch + CA

    // ---- LeFF ----
    ln_kernel<<<gLN, 256>>>(out, lnffn_w, lnffn_b, tmp);
    sgemm64<<<gH, 256>>>(leff_in, tmp, h1, nullptr, HIDDEN, C);
    dwconv_gelu<<<(NB * HIDDEN * HW) / 256, 256>>>(h1, leff_dw, h2);
    sgemm64<<<gC, 256>>>(leff_out, h2, out, out, C, HIDDEN);   // x += leff(...)
}

// round 2
// speedup vs baseline: 1.2313x; 1.2313x over previous
#include <cuda_runtime.h>
#include <math.h>

#define NB 8
#define C 256
#define HW 1024
#define TN 1024
#define HIDDEN 1024

// ---------------- scratch ----------------
__device__ float g_qbranch[NB*C*HW];
__device__ float g_kvbranch[NB*C*HW];
__device__ float g_tmp[NB*C*HW];
__device__ float g_qb[NB*C*HW];
__device__ float g_kb[NB*C*HW];
__device__ float g_vb[NB*C*HW];
__device__ float g_attn[NB*C*HW];
__device__ float g_h1[NB*HIDDEN*HW];   // also: conv split-K partials / qkv-free scratch
__device__ float g_h2[NB*HIDDEN*HW];   // also: fused qkv output

// ---------------- f32x2 helpers ----------------
__device__ __forceinline__ void ffma2(unsigned long long& d, unsigned long long a, unsigned long long b) {
    asm("fma.rn.f32x2 %0, %1, %2, %0;" : "+l"(d) : "l"(a), "l"(b));
}
__device__ __forceinline__ void mul2(unsigned long long& d, unsigned long long a) {
    asm("mul.rn.f32x2 %0, %0, %1;" : "+l"(d) : "l"(a));
}
__device__ __forceinline__ unsigned long long pk2(float x) {
    unsigned u = __float_as_uint(x);
    unsigned long long r;
    asm("mov.b64 %0, {%1, %1};" : "=l"(r) : "r"(u));
    return r;
}
__device__ __forceinline__ float lo2(unsigned long long v){ return __uint_as_float((unsigned)v); }
__device__ __forceinline__ float hi2(unsigned long long v){ return __uint_as_float((unsigned)(v >> 32)); }

// ---------------- cp.async helpers ----------------
__device__ __forceinline__ void cp16(void* dst, const void* src) {
    unsigned d = (unsigned)__cvta_generic_to_shared(dst);
    asm volatile("cp.async.ca.shared.global [%0], [%1], 16;" :: "r"(d), "l"(src));
}
__device__ __forceinline__ void cp4z(void* dst, const void* src, int sz) {
    unsigned d = (unsigned)__cvta_generic_to_shared(dst);
    asm volatile("cp.async.ca.shared.global [%0], [%1], 4, %2;" :: "r"(d), "l"(src), "r"(sz));
}
__device__ __forceinline__ void cp_commit() { asm volatile("cp.async.commit_group;" ::: "memory"); }
__device__ __forceinline__ void cp_wait0()  { asm volatile("cp.async.wait_group 0;" ::: "memory"); }

// ---------------- shared 64x128 f32x2 tile compute ----------------
__device__ __forceinline__ void mm_tile(
    const float (*As)[64], const float (*Bs)[128],
    unsigned long long accp[4][8], int tm0, int cw)
{
    #pragma unroll 4
    for (int k = 0; k < 16; k++) {
        ulonglong2 a01 = *(const ulonglong2*)&As[k][tm0];
        ulonglong2 a23 = *(const ulonglong2*)&As[k][tm0 + 4];
        float4 b0 = *(const float4*)&Bs[k][cw];
        float4 b1 = *(const float4*)&Bs[k][cw + 32];
        unsigned long long ap[4] = {a01.x, a01.y, a23.x, a23.y};
        unsigned long long bb[8] = {pk2(b0.x), pk2(b0.y), pk2(b0.z), pk2(b0.w),
                                    pk2(b1.x), pk2(b1.y), pk2(b1.z), pk2(b1.w)};
        #pragma unroll
        for (int i = 0; i < 4; i++)
            #pragma unroll
            for (int j = 0; j < 8; j++)
                ffma2(accp[i][j], ap[i], bb[j]);
    }
}

// ---------------- batched SGEMM: tile 64(M)x128(N), 128 thr, dbl-buffered ----------------
// grid: (TN/128, M/64, NB*S). If S>1: output to partials at (s*NB+b)*M*TN, add must be null.
__global__ __launch_bounds__(128) void sgemm_f2(
    const float* __restrict__ A, const float* __restrict__ B,
    float* Cd, const float* addp, int M, int K, int S)
{
    __shared__ float As[2][16][64];
    __shared__ float Bs[2][16][128];

    int bz = blockIdx.z;
    int s = bz >> 3, b = bz & 7;
    int bn = blockIdx.x * 128;
    int bm = blockIdx.y * 64;
    int Klen = K / S;
    int k0 = s * Klen;

    const float* Bb = B + (size_t)b * K * TN;
    float*       Cb = Cd + (size_t)(s * NB + b) * M * TN;
    const float* addb = addp ? addp + (size_t)b * M * TN : nullptr;

    int tid = threadIdx.x;
    int warp = tid >> 5, lane = tid & 31;
    int wm = warp >> 1, wn = warp & 1;
    int lm = lane >> 3, ln = lane & 7;
    int tm0 = wm * 32 + lm * 8;
    int cw  = wn * 64 + ln * 4;

    int am = tid & 63, akc = (tid >> 6) * 8;
    const float* aptr = A + (size_t)(bm + am) * K + k0 + akc;

    unsigned long long accp[4][8] = {};

    // prologue
    float4 a0 = *(const float4*)(aptr);
    float4 a1 = *(const float4*)(aptr + 4);
    {
        int kb = (tid >> 5) * 4, n4 = (tid & 31) * 4;
        #pragma unroll
        for (int e = 0; e < 4; e++)
            cp16(&Bs[0][kb + e][n4], Bb + (size_t)(k0 + kb + e) * TN + bn + n4);
    }
    cp_commit();
    #pragma unroll
    for (int j = 0; j < 4; j++) { As[0][akc + j][am] = ((const float*)&a0)[j]; As[0][akc + 4 + j][am] = ((const float*)&a1)[j]; }
    cp_wait0();
    __syncthreads();

    int nk = Klen / 16;
    int buf = 0;
    for (int kt = 0; kt < nk; kt++) {
        bool more = (kt + 1) < nk;
        if (more) {
            const float* ap2 = aptr + (kt + 1) * 16;
            a0 = *(const float4*)(ap2);
            a1 = *(const float4*)(ap2 + 4);
            int kb = (tid >> 5) * 4, n4 = (tid & 31) * 4;
            int kk = k0 + (kt + 1) * 16;
            #pragma unroll
            for (int e = 0; e < 4; e++)
                cp16(&Bs[buf ^ 1][kb + e][n4], Bb + (size_t)(kk + kb + e) * TN + bn + n4);
            cp_commit();
        }
        mm_tile(As[buf], Bs[buf], accp, tm0, cw);
        if (more) {
            #pragma unroll
            for (int j = 0; j < 4; j++) { As[buf ^ 1][akc + j][am] = ((const float*)&a0)[j]; As[buf ^ 1][akc + 4 + j][am] = ((const float*)&a1)[j]; }
            cp_wait0();
        }
        __syncthreads();
        buf ^= 1;
    }

    // epilogue
    #pragma unroll
    for (int mp = 0; mp < 4; mp++) {
        int r = bm + tm0 + 2 * mp;
        float4 vlo1 = make_float4(lo2(accp[mp][0]), lo2(accp[mp][1]), lo2(accp[mp][2]), lo2(accp[mp][3]));
        float4 vhi1 = make_float4(hi2(accp[mp][0]), hi2(accp[mp][1]), hi2(accp[mp][2]), hi2(accp[mp][3]));
        float4 vlo2 = make_float4(lo2(accp[mp][4]), lo2(accp[mp][5]), lo2(accp[mp][6]), lo2(accp[mp][7]));
        float4 vhi2 = make_float4(hi2(accp[mp][4]), hi2(accp[mp][5]), hi2(accp[mp][6]), hi2(accp[mp][7]));
        size_t o1 = (size_t)r * TN + bn + cw;
        size_t o2 = o1 + 32;
        size_t o1b = o1 + TN, o2b = o2 + TN;
        if (addb) {
            float4 t;
            t = *(const float4*)(addb + o1);  vlo1.x += t.x; vlo1.y += t.y; vlo1.z += t.z; vlo1.w += t.w;
            t = *(const float4*)(addb + o2);  vlo2.x += t.x; vlo2.y += t.y; vlo2.z += t.z; vlo2.w += t.w;
            t = *(const float4*)(addb + o1b); vhi1.x += t.x; vhi1.y += t.y; vhi1.z += t.z; vhi1.w += t.w;
            t = *(const float4*)(addb + o2b); vhi2.x += t.x; vhi2.y += t.y; vhi2.z += t.z; vhi2.w += t.w;
        }
        *(float4*)(Cb + o1)  = vlo1;
        *(float4*)(Cb + o2)  = vlo2;
        *(float4*)(Cb + o1b) = vhi1;
        *(float4*)(Cb + o2b) = vhi2;
    }
}

// ---------------- conv KxK implicit GEMM, same tiling, split-K ----------------
template<int KW, int PAD>
__global__ __launch_bounds__(128) void conv_f2(
    const float* __restrict__ Wt, const float* __restrict__ X, float* __restrict__ Cd, int S)
{
    constexpr int KK2 = KW * KW;
    constexpr int K = C * KK2;
    __shared__ float As[2][16][64];
    __shared__ float Bs[2][16][128];

    int bz = blockIdx.z;
    int s = bz >> 3, b = bz & 7;
    int bn = blockIdx.x * 128;
    int bm = blockIdx.y * 64;
    int Klen = K / S;
    int k0 = s * Klen;

    const float* Xb = X + (size_t)b * C * HW;
    float*       Cb = Cd + (size_t)(s * NB + b) * C * HW;

    int tid = threadIdx.x;
    int warp = tid >> 5, lane = tid & 31;
    int wm = warp >> 1, wn = warp & 1;
    int lm = lane >> 3, ln = lane & 7;
    int tm0 = wm * 32 + lm * 8;
    int cw  = wn * 64 + ln * 4;

    int am = tid & 63, akc = (tid >> 6) * 8;
    const float* aptr = Wt + (size_t)(bm + am) * K + k0 + akc;

    int n = bn + tid;            // this thread's pixel column for B gather (tid<128)
    int yy = n >> 5, xx = n & 31;

    unsigned long long accp[4][8] = {};

    // B gather for one 16-k stage
    auto gatherB = [&](int buf, int kk) {
        #pragma unroll
        for (int e = 0; e < 16; e++) {
            int kg = kk + e;
            int ic = kg / KK2;
            int tap = kg - ic * KK2;
            int dy = tap / KW, dx = tap - dy * KW;
            int iy = yy + dy - PAD, ix = xx + dx - PAD;
            bool ok = ((unsigned)iy < 32u) && ((unsigned)ix < 32u);
            const float* src = Xb + (size_t)ic * HW + (ok ? ((iy << 5) + ix) : 0);
            cp4z(&Bs[buf][e][tid], src, ok ? 4 : 0);
        }
    };

    // prologue
    float4 a0 = *(const float4*)(aptr);
    float4 a1 = *(const float4*)(aptr + 4);
    gatherB(0, k0);
    cp_commit();
    #pragma unroll
    for (int j = 0; j < 4; j++) { As[0][akc + j][am] = ((const float*)&a0)[j]; As[0][akc + 4 + j][am] = ((const float*)&a1)[j]; }
    cp_wait0();
    __syncthreads();

    int nk = Klen / 16;
    int buf = 0;
    for (int kt = 0; kt < nk; kt++) {
        bool more = (kt + 1) < nk;
        if (more) {
            const float* ap2 = aptr + (kt + 1) * 16;
            a0 = *(const float4*)(ap2);
            a1 = *(const float4*)(ap2 + 4);
            gatherB(buf ^ 1, k0 + (kt + 1) * 16);
            cp_commit();
        }
        mm_tile(As[buf], Bs[buf], accp, tm0, cw);
        if (more) {
            #pragma unroll
            for (int j = 0; j < 4; j++) { As[buf ^ 1][akc + j][am] = ((const float*)&a0)[j]; As[buf ^ 1][akc + 4 + j][am] = ((const float*)&a1)[j]; }
            cp_wait0();
        }
        __syncthreads();
        buf ^= 1;
    }

    #pragma unroll
    for (int mp = 0; mp < 4; mp++) {
        int r = bm + tm0 + 2 * mp;
        size_t o1 = (size_t)r * TN + bn + cw;
        *(float4*)(Cb + o1)      = make_float4(lo2(accp[mp][0]), lo2(accp[mp][1]), lo2(accp[mp][2]), lo2(accp[mp][3]));
        *(float4*)(Cb + o1 + 32) = make_float4(lo2(accp[mp][4]), lo2(accp[mp][5]), lo2(accp[mp][6]), lo2(accp[mp][7]));
        *(float4*)(Cb + o1 + TN)      = make_float4(hi2(accp[mp][0]), hi2(accp[mp][1]), hi2(accp[mp][2]), hi2(accp[mp][3]));
        *(float4*)(Cb + o1 + TN + 32) = make_float4(hi2(accp[mp][4]), hi2(accp[mp][5]), hi2(accp[mp][6]), hi2(accp[mp][7]));
    }
}

// ---------------- split-K reduction (n = NB*C*HW fixed) ----------------
__global__ __launch_bounds__(256) void reduce_add(
    float* __restrict__ dst, const float* __restrict__ part, int S, int addto)
{
    size_t i = ((size_t)blockIdx.x * 256 + threadIdx.x) * 4;
    float4 acc;
    if (addto) acc = *(const float4*)(dst + i);
    else acc = make_float4(0.f, 0.f, 0.f, 0.f);
    for (int s = 0; s < S; s++) {
        float4 p = *(const float4*)(part + (size_t)s * (NB * C * HW) + i);
        acc.x += p.x; acc.y += p.y; acc.z += p.z; acc.w += p.w;
    }
    *(float4*)(dst + i) = acc;
}

// ---------------- layernorm over channels ----------------
__global__ __launch_bounds__(256) void ln_kernel(
    const float* __restrict__ x, const float* __restrict__ w,
    const float* __restrict__ bias, float* __restrict__ y)
{
    int b = blockIdx.y;
    int n0 = blockIdx.x * 32;
    int nx = threadIdx.x & 31;
    int cg = threadIdx.x >> 5;
    const float* xb = x + (size_t)b * C * HW + n0 + nx;

    float v[32];
    float s = 0.f, ss = 0.f;
    #pragma unroll
    for (int i = 0; i < 32; i++) {
        float t = xb[(size_t)(cg * 32 + i) * HW];
        v[i] = t; s += t; ss += t * t;
    }
    __shared__ float rs[8][32], rss[8][32];
    rs[cg][nx] = s; rss[cg][nx] = ss;
    __syncthreads();
    float tot = 0.f, tot2 = 0.f;
    #pragma unroll
    for (int g = 0; g < 8; g++) { tot += rs[g][nx]; tot2 += rss[g][nx]; }
    float mu = tot * (1.f / 256.f);
    float var = tot2 * (1.f / 256.f) - mu * mu;
    float rstd = rsqrtf(var + 1e-5f);

    float* yb = y + (size_t)b * C * HW + n0 + nx;
    #pragma unroll
    for (int i = 0; i < 32; i++) {
        int c = cg * 32 + i;
        yb[(size_t)c * HW] = (v[i] - mu) * rstd * w[c] + bias[c];
    }
}

// ---------------- fused flash attention (d=64, N=1024), f32x2 inner loops ----------------
__global__ __launch_bounds__(256) void attn64(
    const float* __restrict__ Q, const float* __restrict__ Kg,
    const float* __restrict__ V, float* __restrict__ O, size_t bstride)
{
    extern __shared__ float sm[];
    float (*Qs)[64] = (float(*)[64])(sm);
    float (*Ks)[64] = (float(*)[64])(sm + 4096);
    float (*Vs)[68] = (float(*)[68])(sm + 8192);
    float (*Ps)[68] = (float(*)[68])(sm + 8192 + 4352);

    int n0 = blockIdx.x * 64;
    size_t ib = (size_t)blockIdx.z * bstride + (size_t)blockIdx.y * 64 * HW;
    size_t ob = ((size_t)blockIdx.z * C + (size_t)blockIdx.y * 64) * (size_t)HW;
    const float* Qb = Q + ib;
    const float* Kb = Kg + ib;
    const float* Vb = V + ib;

    int tid = threadIdx.x;
    int tx = tid & 15, ty = tid >> 4;

    for (int idx = tid; idx < 4096; idx += 256) {
        int d = idx >> 6, q = idx & 63;
        Qs[d][q] = Qb[(size_t)d * HW + n0 + q];
    }

    unsigned long long op[4][2] = {};
    float mrun[4], lrun[4];
    #pragma unroll
    for (int i = 0; i < 4; i++) { mrun[i] = -1e30f; lrun[i] = 0.f; }

    for (int m0 = 0; m0 < HW; m0 += 64) {
        __syncthreads();
        for (int idx = tid; idx < 4096; idx += 256) {
            int d = idx >> 6, m = idx & 63;
            Ks[d][m] = Kb[(size_t)d * HW + m0 + m];
            Vs[m][d] = Vb[(size_t)d * HW + m0 + m];
        }
        __syncthreads();

        unsigned long long sp[4][2] = {};
        #pragma unroll 8
        for (int d = 0; d < 64; d++) {
            float4 av = *(const float4*)&Qs[d][ty << 2];
            ulonglong2 bp = *(const ulonglong2*)&Ks[d][tx << 2];
            unsigned long long a0 = pk2(av.x), a1 = pk2(av.y), a2 = pk2(av.z), a3 = pk2(av.w);
            ffma2(sp[0][0], a0, bp.x); ffma2(sp[0][1], a0, bp.y);
            ffma2(sp[1][0], a1, bp.x); ffma2(sp[1][1], a1, bp.y);
            ffma2(sp[2][0], a2, bp.x); ffma2(sp[2][1], a2, bp.y);
            ffma2(sp[3][0], a3, bp.x); ffma2(sp[3][1], a3, bp.y);
        }
        float s[4][4];
        #pragma unroll
        for (int i = 0; i < 4; i++) {
            s[i][0] = lo2(sp[i][0]) * 0.125f;
            s[i][1] = hi2(sp[i][0]) * 0.125f;
            s[i][2] = lo2(sp[i][1]) * 0.125f;
            s[i][3] = hi2(sp[i][1]) * 0.125f;
        }

        #pragma unroll
        for (int i = 0; i < 4; i++) {
            float mx = fmaxf(fmaxf(s[i][0], s[i][1]), fmaxf(s[i][2], s[i][3]));
            #pragma unroll
            for (int o = 1; o < 16; o <<= 1)
                mx = fmaxf(mx, __shfl_xor_sync(0xffffffffu, mx, o));
            float mnew = fmaxf(mrun[i], mx);
            float corr = __expf(mrun[i] - mnew);
            float rsum = 0.f;
            #pragma unroll
            for (int j = 0; j < 4; j++) {
                float p = __expf(s[i][j] - mnew);
                s[i][j] = p; rsum += p;
            }
            #pragma unroll
            for (int o = 1; o < 16; o <<= 1)
                rsum += __shfl_xor_sync(0xffffffffu, rsum, o);
            lrun[i] = lrun[i] * corr + rsum;
            mrun[i] = mnew;
            unsigned long long cp = pk2(corr);
            mul2(op[i][0], cp); mul2(op[i][1], cp);
            #pragma unroll
            for (int j = 0; j < 4; j++) Ps[(ty << 2) + i][(tx << 2) + j] = s[i][j];
        }
        __syncthreads();

        #pragma unroll 8
        for (int m = 0; m < 64; m++) {
            ulonglong2 vp = *(const ulonglong2*)&Vs[m][tx << 2];
            unsigned long long a0 = pk2(Ps[(ty << 2) + 0][m]);
            unsigned long long a1 = pk2(Ps[(ty << 2) + 1][m]);
            unsigned long long a2 = pk2(Ps[(ty << 2) + 2][m]);
            unsigned long long a3 = pk2(Ps[(ty << 2) + 3][m]);
            ffma2(op[0][0], a0, vp.x); ffma2(op[0][1], a0, vp.y);
            ffma2(op[1][0], a1, vp.x); ffma2(op[1][1], a1, vp.y);
            ffma2(op[2][0], a2, vp.x); ffma2(op[2][1], a2, vp.y);
            ffma2(op[3][0], a3, vp.x); ffma2(op[3][1], a3, vp.y);
        }
    }

    float* Ob = O + ob;
    #pragma unroll
    for (int i = 0; i < 4; i++) {
        float linv = 1.f / lrun[i];
        #pragma unroll
        for (int j = 0; j < 4; j++) {
            float v = (j & 1) ? hi2(op[i][j >> 1]) : lo2(op[i][j >> 1]);
            Ob[(size_t)((tx << 2) + j) * HW + n0 + (ty << 2) + i] = v * linv;
        }
    }
}

// ---------------- depthwise 3x3 conv + exact GELU ----------------
__global__ __launch_bounds__(256) void dwconv_gelu(
    const float* __restrict__ X, const float* __restrict__ W, float* __restrict__ Y)
{
    int idx = blockIdx.x * 256 + threadIdx.x;
    int x = idx & 31;
    int y = (idx >> 5) & 31;
    int c = (idx >> 10) & 1023;
    int b = idx >> 20;
    const float* xb = X + ((size_t)b * HIDDEN + c) * HW;
    const float* wc = W + c * 9;
    float acc = 0.f;
    #pragma unroll
    for (int dy = 0; dy < 3; dy++) {
        int iy = y + dy - 1;
        #pragma unroll
        for (int dx = 0; dx < 3; dx++) {
            int ix = x + dx - 1;
            if ((unsigned)iy < 32u && (unsigned)ix < 32u)
                acc += wc[dy * 3 + dx] * xb[(iy << 5) + ix];
        }
    }
    float g = 0.5f * acc * (1.f + erff(acc * 0.70710678118654752440f));
    Y[idx] = g;
}

// ---------------- host orchestration ----------------
extern "C" void kernel_launch(void* const* d_in, const int* in_sizes, int n_in,
                              void* d_out, int out_size)
{
    const float* aop      = (const float*)d_in[0];
    const float* dop      = (const float*)d_in[1];
    const float* w_qconv  = (const float*)d_in[2];
    const float* w_kvconv = (const float*)d_in[3];
    const float* lnq1_w   = (const float*)d_in[4];
    const float* lnq1_b   = (const float*)d_in[5];
    const float* lnkv1_w  = (const float*)d_in[6];
    const float* lnkv1_b  = (const float*)d_in[7];
    const float* lnq2_w   = (const float*)d_in[8];
    const float* lnq2_b   = (const float*)d_in[9];
    const float* lnkv2_w  = (const float*)d_in[10];
    const float* lnkv2_b  = (const float*)d_in[11];
    const float* lnffn_w  = (const float*)d_in[12];
    const float* lnffn_b  = (const float*)d_in[13];
    const float* saq_qkv  = (const float*)d_in[14];
    const float* saq_proj = (const float*)d_in[15];
    const float* sakv_qkv = (const float*)d_in[16];
    const float* sakv_proj= (const float*)d_in[17];
    const float* ca_q     = (const float*)d_in[18];
    const float* ca_k     = (const float*)d_in[19];
    const float* ca_v     = (const float*)d_in[20];
    const float* ca_proj  = (const float*)d_in[21];
    const float* leff_in  = (const float*)d_in[22];
    const float* leff_dw  = (const float*)d_in[23];
    const float* leff_out = (const float*)d_in[24];
    float* out = (float*)d_out;

    float *qbr, *kvbr, *tmp, *qb, *kb, *vb, *att, *h1, *h2;
    cudaGetSymbolAddress((void**)&qbr,  g_qbranch);
    cudaGetSymbolAddress((void**)&kvbr, g_kvbranch);
    cudaGetSymbolAddress((void**)&tmp,  g_tmp);
    cudaGetSymbolAddress((void**)&qb,   g_qb);
    cudaGetSymbolAddress((void**)&kb,   g_kb);
    cudaGetSymbolAddress((void**)&vb,   g_vb);
    cudaGetSymbolAddress((void**)&att,  g_attn);
    cudaGetSymbolAddress((void**)&h1,   g_h1);
    cudaGetSymbolAddress((void**)&h2,   g_h2);

    const int ATTN_SMEM = (4096 + 4096 + 4352 + 4352) * 4;
    cudaFuncSetAttribute(attn64, cudaFuncAttributeMaxDynamicSharedMemorySize, ATTN_SMEM);

    dim3 gC(8, 4, NB);          // M = 256
    dim3 gQKV(8, 12, NB);       // M = 768
    dim3 gHID(8, 16, NB);       // M = 1024
    dim3 gCS4(8, 4, NB * 4);    // M = 256, split-K 4
    dim3 gCS2(8, 4, NB * 2);    // M = 256, split-K 2
    dim3 gLN(32, NB);
    dim3 gATT(16, 4, NB);
    size_t strideQKV = (size_t)768 * HW;
    size_t strideC   = (size_t)C * HW;

    // ---- q branch ----
    conv_f2<3, 1><<<gCS4, 128>>>(w_qconv, aop, h1, 4);
    reduce_add<<<2048, 256>>>(qbr, h1, 4, 0);
    ln_kernel<<<gLN, 256>>>(qbr, lnq1_w, lnq1_b, tmp);
    sgemm_f2<<<gQKV, 128>>>(saq_qkv, tmp, h2, nullptr, 768, C, 1);
    attn64<<<gATT, 256, ATTN_SMEM>>>(h2, h2 + 256 * HW, h2 + 512 * HW, att, strideQKV);
    sgemm_f2<<<gC, 128>>>(saq_proj, att, qbr, qbr, C, C, 1);

    // ---- kv branch ----
    conv_f2<5, 2><<<gCS4, 128>>>(w_kvconv, dop, h1, 4);
    reduce_add<<<2048, 256>>>(kvbr, h1, 4, 0);
    ln_kernel<<<gLN, 256>>>(kvbr, lnkv1_w, lnkv1_b, tmp);
    sgemm_f2<<<gQKV, 128>>>(sakv_qkv, tmp, h2, nullptr, 768, C, 1);
    attn64<<<gATT, 256, ATTN_SMEM>>>(h2, h2 + 256 * HW, h2 + 512 * HW, att, strideQKV);
    sgemm_f2<<<gC, 128>>>(sakv_proj, att, kvbr, kvbr, C, C, 1);

    // ---- cross attention ----
    ln_kernel<<<gLN, 256>>>(qbr, lnq2_w, lnq2_b, tmp);
    sgemm_f2<<<gC, 128>>>(ca_q, tmp, qb, nullptr, C, C, 1);
    ln_kernel<<<gLN, 256>>>(kvbr, lnkv2_w, lnkv2_b, tmp);
    sgemm_f2<<<gC, 128>>>(ca_k, tmp, kb, nullptr, C, C, 1);
    sgemm_f2<<<gC, 128>>>(ca_v, tmp, vb, nullptr, C, C, 1);
    attn64<<<gATT, 256, ATTN_SMEM>>>(qb, kb, vb, att, strideC);
    sgemm_f2<<<gC, 128>>>(ca_proj, att, out, qbr, C, C, 1);

    // ---- LeFF ----
    ln_kernel<<<gLN, 256>>>(out, lnffn_w, lnffn_b, tmp);
    sgemm_f2<<<gHID, 128>>>(leff_in, tmp, h1, nullptr, HIDDEN, C, 1);
    dwconv_gelu<<<(NB * HIDDEN * HW) / 256, 256>>>(h1, leff_dw, h2);
    sgemm_f2<<<gCS2, 128>>>(leff_out, h2, h1, nullptr, C, HIDDEN, 2);
    reduce_add<<<2048, 256>>>(out, h1, 2, 1);
}